// round 6
// baseline (speedup 1.0000x reference)
#include <cuda_runtime.h>

#define LH 128
#define LP 32
#define DM 64
#define HID 64
#define MAXLEN 128
#define ST 68      // activation row stride (floats): conflict-free strided LDS.128
#define KST 80     // kv row stride
#define HOFF 20    // kv per-head word offset (banks disjoint across heads)
#define PST 64     // weight panel stride (broadcast reads -> no conflicts)

typedef unsigned long long u64;

__device__ __forceinline__ u64 pk2(float lo, float hi) {
    u64 r; asm("mov.b64 %0,{%1,%2};" : "=l"(r) : "f"(lo), "f"(hi)); return r;
}
__device__ __forceinline__ void fma2(u64& d, u64 a, u64 b) {
    asm("fma.rn.f32x2 %0,%1,%2,%3;" : "=l"(d) : "l"(a), "l"(b), "l"(d));
}
__device__ __forceinline__ void mul2(u64& d, u64 a, u64 b) {
    asm("mul.rn.f32x2 %0,%1,%2;" : "=l"(d) : "l"(a), "l"(b));
}
__device__ __forceinline__ float2 up2(u64 v) {
    float2 r; asm("mov.b64 {%0,%1},%2;" : "=f"(r.x), "=f"(r.y) : "l"(v)); return r;
}

// smem layout (floats): total 57344 floats = 229376 bytes
#define O_X  0                  // [128][ST] hla -> h1a
#define O_C  (128*ST)           // [128][ST] pep(rows0-31) -> LN(ctx) -> h1b
#define O_Q  (2*128*ST)         // [128][ST] q -> z
#define O_KV (3*128*ST)         // [32][KST]
#define O_P0 (O_KV + LP*KST)    // W_hla panel [64][PST]
#define O_P1 (O_P0 + 4096)      // W_pep
#define O_P2 (O_P1 + 4096)      // W1a (cols 0..63)
#define O_P3 (O_P2 + 4096)      // W1b (cols 64..127)
#define O_P4 (O_P3 + 4096)      // W2a (rows 0..63)
#define O_P5 (O_P4 + 4096)      // W2b (rows 64..127)
#define O_P6 (O_P5 + 4096)      // W_out
#define SMEM_FLOATS (O_P6 + 4096)
#define SMEM_BYTES  (SMEM_FLOATS * 4)

// load a 64x64 panel (1024 float4 over 512 threads)
__device__ __forceinline__ void load_panel(float* dst, const float* __restrict__ g,
                                           int rowlen, int col0, int t) {
    #pragma unroll
    for (int i = 0; i < 2; i++) {
        int idx = i * 512 + t;
        int k = idx >> 4, c = (idx & 15) * 4;
        *(float4*)&dst[k * PST + c] = __ldg((const float4*)(g + k * rowlen + col0 + c));
    }
}

__device__ __forceinline__ void bias8(u64 a[4], const float* __restrict__ b, int cw) {
    float4 x = __ldg((const float4*)(b + cw));
    float4 y = __ldg((const float4*)(b + cw + 4));
    a[0] = pk2(x.x, x.y); a[1] = pk2(x.z, x.w);
    a[2] = pk2(y.x, y.y); a[3] = pk2(y.z, y.w);
}

__device__ __forceinline__ void gelu4(u64 a[4]) {
    #pragma unroll
    for (int i = 0; i < 4; i++) {
        float2 f = up2(a[i]);
        f.x *= normcdff(f.x);
        f.y *= normcdff(f.y);
        a[i] = pk2(f.x, f.y);
    }
}

// acc[r] += A[row0 + 32r][0..63] * W[0..63][cw..cw+7]; W reads are warp-broadcast.
template<int R>
__device__ __forceinline__ void gemmP(const float* __restrict__ sA, int row0,
                                      const float* __restrict__ sW, int cw,
                                      u64 acc[][4]) {
    #pragma unroll 4
    for (int k0 = 0; k0 < 64; k0 += 4) {
        float4 a[R];
        #pragma unroll
        for (int r = 0; r < R; r++)
            a[r] = *(const float4*)&sA[(row0 + r * 32) * ST + k0];
        #pragma unroll
        for (int j = 0; j < 4; j++) {
            const float* wr = &sW[(k0 + j) * PST + cw];
            ulonglong2 w0 = *(const ulonglong2*)wr;
            ulonglong2 w1 = *(const ulonglong2*)(wr + 4);
            #pragma unroll
            for (int r = 0; r < R; r++) {
                float av = (j == 0) ? a[r].x : (j == 1) ? a[r].y
                         : (j == 2) ? a[r].z : a[r].w;
                u64 d = pk2(av, av);
                fma2(acc[r][0], d, w0.x);
                fma2(acc[r][1], d, w0.y);
                fma2(acc[r][2], d, w1.x);
                fma2(acc[r][3], d, w1.y);
            }
        }
    }
}

__device__ __forceinline__ void store_tile(float* dst, int row0, int cw, const u64 a[][4]) {
    #pragma unroll
    for (int r = 0; r < 2; r++) {
        float2 f0 = up2(a[r][0]), f1 = up2(a[r][1]);
        float2 f2 = up2(a[r][2]), f3 = up2(a[r][3]);
        float* p = dst + (row0 + r * 32) * ST + cw;
        *(float4*)p       = make_float4(f0.x, f0.y, f1.x, f1.y);
        *(float4*)(p + 4) = make_float4(f2.x, f2.y, f3.x, f3.y);
    }
}

__global__ __launch_bounds__(512, 1)
void h2p_kernel(const float* __restrict__ hla_in,
                const float* __restrict__ pep_in,
                const float* __restrict__ W_hla, const float* __restrict__ b_hla,
                const float* __restrict__ W_pep, const float* __restrict__ b_pep,
                const float* __restrict__ rel_bias,
                const float* __restrict__ ln_g, const float* __restrict__ ln_b,
                const float* __restrict__ W1, const float* __restrict__ b1,
                const float* __restrict__ W2, const float* __restrict__ b2,
                const float* __restrict__ W_out, const float* __restrict__ b_out,
                float* __restrict__ out, int B)
{
    extern __shared__ float sm[];
    const int t  = threadIdx.x;
    const int w  = t >> 5, l = t & 31;
    const int cg = w & 7, rh = w >> 3;
    const int cw = cg * 8;            // cols cw..cw+7
    const int r0 = rh * 64 + l;       // rows r0, r0+32

    // ---- resident weight panels (once per CTA) ----
    load_panel(sm + O_P0, W_hla, HID, 0, t);
    load_panel(sm + O_P1, W_pep, HID, 0, t);
    load_panel(sm + O_P2, W1, 2 * HID, 0, t);
    load_panel(sm + O_P3, W1, 2 * HID, HID, t);
    load_panel(sm + O_P4, W2, HID, 0, t);
    load_panel(sm + O_P5, W2 + HID * HID, HID, 0, t);
    load_panel(sm + O_P6, W_out, DM, 0, t);

    for (int batch = blockIdx.x; batch < B; batch += gridDim.x) {
        // ---- P0: stage hla -> X, pep -> C ----
        {
            const float4* hg = (const float4*)(hla_in + (size_t)batch * LH * DM);
            #pragma unroll
            for (int i = 0; i < 4; i++) {
                int idx = i * 512 + t;
                int rr = idx >> 4, c4 = idx & 15;
                *(float4*)&sm[O_X + rr * ST + c4 * 4] = hg[idx];
            }
            const float4* pg = (const float4*)(pep_in + (size_t)batch * LP * DM);
            int rr = t >> 4, c4 = t & 15;
            *(float4*)&sm[O_C + rr * ST + c4 * 4] = pg[t];
        }
        __syncthreads();   // S0 (also orders panel STS before first use)

        // ---- P1: q = hla @ W_hla + b_hla -> Q ; kv (warps 8-15) ----
        {
            u64 qa[2][4];
            bias8(qa[0], b_hla, cw);
            qa[1][0] = qa[0][0]; qa[1][1] = qa[0][1];
            qa[1][2] = qa[0][2]; qa[1][3] = qa[0][3];
            gemmP<2>(&sm[O_X], r0, &sm[O_P0], cw, qa);
            store_tile(&sm[O_Q], r0, cw, qa);
        }
        if (t >= 256) {
            int kcw = (w - 8) * 8;
            u64 ka[1][4];
            bias8(ka[0], b_pep, kcw);
            gemmP<1>(&sm[O_C], l, &sm[O_P1], kcw, ka);
            float2 f0 = up2(ka[0][0]), f1 = up2(ka[0][1]);
            float2 f2 = up2(ka[0][2]), f3 = up2(ka[0][3]);
            float* kd = &sm[O_KV + l * KST + (kcw >> 4) * HOFF + (kcw & 15)];
            *(float4*)kd       = make_float4(f0.x, f0.y, f1.x, f1.y);
            *(float4*)(kd + 4) = make_float4(f2.x, f2.y, f3.x, f3.y);
        }
        __syncthreads();   // S1

        // ---- P2: attention + LN -> C ----
        {
            const int r = t >> 2, h = t & 3;
            const float* qrow = &sm[O_Q + r * ST + h * 16];
            ulonglong2 qA = *(const ulonglong2*)(qrow + 0);
            ulonglong2 qB = *(const ulonglong2*)(qrow + 4);
            ulonglong2 qC = *(const ulonglong2*)(qrow + 8);
            ulonglong2 qD = *(const ulonglong2*)(qrow + 12);

            float sc[32];
            const float* brow = rel_bias + h * (MAXLEN * MAXLEN) + r * MAXLEN;
            #pragma unroll
            for (int k4 = 0; k4 < 8; k4++) {
                float4 bv = __ldg((const float4*)&brow[k4 * 4]);
                sc[k4*4+0] = bv.x; sc[k4*4+1] = bv.y;
                sc[k4*4+2] = bv.z; sc[k4*4+3] = bv.w;
            }
            #pragma unroll
            for (int k = 0; k < LP; k++) {
                const float* kr = &sm[O_KV + k * KST + h * HOFF];
                ulonglong2 v0 = *(const ulonglong2*)(kr + 0);
                ulonglong2 v1 = *(const ulonglong2*)(kr + 4);
                ulonglong2 v2 = *(const ulonglong2*)(kr + 8);
                ulonglong2 v3 = *(const ulonglong2*)(kr + 12);
                u64 s;
                mul2(s, qA.x, v0.x);
                fma2(s, qA.y, v0.y);
                fma2(s, qB.x, v1.x);
                fma2(s, qB.y, v1.y);
                fma2(s, qC.x, v2.x);
                fma2(s, qC.y, v2.y);
                fma2(s, qD.x, v3.x);
                fma2(s, qD.y, v3.y);
                float2 sp = up2(s);
                sc[k] = fmaf(0.25f, sp.x + sp.y, sc[k]);
            }
            float mx = sc[0];
            #pragma unroll
            for (int k = 1; k < LP; k++) mx = fmaxf(mx, sc[k]);
            float ssum = 0.f;
            #pragma unroll
            for (int k = 0; k < LP; k++) { sc[k] = __expf(sc[k] - mx); ssum += sc[k]; }
            float inv = 1.0f / ssum;

            u64 cx[8];
            #pragma unroll
            for (int i = 0; i < 8; i++) cx[i] = 0ull;
            #pragma unroll
            for (int k = 0; k < LP; k++) {
                const float* kr = &sm[O_KV + k * KST + h * HOFF];
                ulonglong2 v0 = *(const ulonglong2*)(kr + 0);
                ulonglong2 v1 = *(const ulonglong2*)(kr + 4);
                ulonglong2 v2 = *(const ulonglong2*)(kr + 8);
                ulonglong2 v3 = *(const ulonglong2*)(kr + 12);
                u64 pd = pk2(sc[k], sc[k]);
                fma2(cx[0], pd, v0.x); fma2(cx[1], pd, v0.y);
                fma2(cx[2], pd, v1.x); fma2(cx[3], pd, v1.y);
                fma2(cx[4], pd, v2.x); fma2(cx[5], pd, v2.y);
                fma2(cx[6], pd, v3.x); fma2(cx[7], pd, v3.y);
            }
            float x[16];
            #pragma unroll
            for (int i = 0; i < 8; i++) {
                float2 f = up2(cx[i]);
                x[2*i]   = f.x * inv;
                x[2*i+1] = f.y * inv;
            }
            float s1 = 0.f, s2 = 0.f;
            #pragma unroll
            for (int i = 0; i < 16; i++) { s1 += x[i]; s2 = fmaf(x[i], x[i], s2); }
            s1 += __shfl_xor_sync(0xffffffffu, s1, 1);
            s2 += __shfl_xor_sync(0xffffffffu, s2, 1);
            s1 += __shfl_xor_sync(0xffffffffu, s1, 2);
            s2 += __shfl_xor_sync(0xffffffffu, s2, 2);
            float mu   = s1 * (1.0f / 64.0f);
            float var  = s2 * (1.0f / 64.0f) - mu * mu;
            float rstd = rsqrtf(var + 1e-5f);
            #pragma unroll
            for (int c4 = 0; c4 < 4; c4++) {
                float4 gv = __ldg((const float4*)&ln_g[h * 16 + c4 * 4]);
                float4 bv = __ldg((const float4*)&ln_b[h * 16 + c4 * 4]);
                float4 o;
                o.x = (x[c4*4+0] - mu) * rstd * gv.x + bv.x;
                o.y = (x[c4*4+1] - mu) * rstd * gv.y + bv.y;
                o.z = (x[c4*4+2] - mu) * rstd * gv.z + bv.z;
                o.w = (x[c4*4+3] - mu) * rstd * gv.w + bv.w;
                *(float4*)&sm[O_C + r * ST + h * 16 + c4 * 4] = o;
            }
        }
        __syncthreads();   // S2

        // ---- P3: h1a -> X ; h1b -> regs ----
        u64 hb[2][4];
        {
            u64 ha[2][4];
            bias8(ha[0], b1, cw);
            ha[1][0] = ha[0][0]; ha[1][1] = ha[0][1];
            ha[1][2] = ha[0][2]; ha[1][3] = ha[0][3];
            gemmP<2>(&sm[O_C], r0, &sm[O_P2], cw, ha);
            gelu4(ha[0]); gelu4(ha[1]);
            store_tile(&sm[O_X], r0, cw, ha);

            bias8(hb[0], b1 + HID, cw);
            hb[1][0] = hb[0][0]; hb[1][1] = hb[0][1];
            hb[1][2] = hb[0][2]; hb[1][3] = hb[0][3];
            gemmP<2>(&sm[O_C], r0, &sm[O_P3], cw, hb);
            gelu4(hb[0]); gelu4(hb[1]);
        }
        __syncthreads();   // S3

        // ---- P4: h1b -> C ----
        store_tile(&sm[O_C], r0, cw, hb);
        __syncthreads();   // S4

        // ---- P5: oacc = b2 + h1a@W2a + h1b@W2b ; P6: z = q + oacc -> Q ----
        {
            u64 oa[2][4];
            bias8(oa[0], b2, cw);
            oa[1][0] = oa[0][0]; oa[1][1] = oa[0][1];
            oa[1][2] = oa[0][2]; oa[1][3] = oa[0][3];
            gemmP<2>(&sm[O_X], r0, &sm[O_P4], cw, oa);
            gemmP<2>(&sm[O_C], r0, &sm[O_P5], cw, oa);
            #pragma unroll
            for (int r = 0; r < 2; r++) {
                float* qp = &sm[O_Q + (r0 + r * 32) * ST + cw];
                float4 q0 = *(const float4*)qp;
                float4 q1 = *(const float4*)(qp + 4);
                float2 f0 = up2(oa[r][0]), f1 = up2(oa[r][1]);
                float2 f2 = up2(oa[r][2]), f3 = up2(oa[r][3]);
                *(float4*)qp       = make_float4(q0.x + f0.x, q0.y + f0.y,
                                                 q0.z + f1.x, q0.w + f1.y);
                *(float4*)(qp + 4) = make_float4(q1.x + f2.x, q1.y + f2.y,
                                                 q1.z + f3.x, q1.w + f3.y);
            }
        }
        __syncthreads();   // S5

        // ---- P7: out = z @ W_out + b_out ----
        {
            u64 ya[2][4];
            bias8(ya[0], b_out, cw);
            ya[1][0] = ya[0][0]; ya[1][1] = ya[0][1];
            ya[1][2] = ya[0][2]; ya[1][3] = ya[0][3];
            gemmP<2>(&sm[O_Q], r0, &sm[O_P6], cw, ya);
            float* ob = out + (size_t)batch * LH * DM;
            #pragma unroll
            for (int r = 0; r < 2; r++) {
                float2 f0 = up2(ya[r][0]), f1 = up2(ya[r][1]);
                float2 f2 = up2(ya[r][2]), f3 = up2(ya[r][3]);
                float* op = ob + (r0 + r * 32) * DM + cw;
                *(float4*)op       = make_float4(f0.x, f0.y, f1.x, f1.y);
                *(float4*)(op + 4) = make_float4(f2.x, f2.y, f3.x, f3.y);
            }
        }
        __syncthreads();   // S6: all z reads done before next iter writes Q
    }
}

extern "C" void kernel_launch(void* const* d_in, const int* in_sizes, int n_in,
                              void* d_out, int out_size)
{
    const float* hla_in   = (const float*)d_in[0];
    const float* pep_in   = (const float*)d_in[1];
    const float* W_hla    = (const float*)d_in[2];
    const float* b_hla    = (const float*)d_in[3];
    const float* W_pep    = (const float*)d_in[4];
    const float* b_pep    = (const float*)d_in[5];
    const float* rel_bias = (const float*)d_in[6];
    const float* ln_g     = (const float*)d_in[7];
    const float* ln_b     = (const float*)d_in[8];
    const float* W1       = (const float*)d_in[9];
    const float* b1       = (const float*)d_in[10];
    const float* W2       = (const float*)d_in[11];
    const float* b2       = (const float*)d_in[12];
    const float* W_out    = (const float*)d_in[13];
    const float* b_out    = (const float*)d_in[14];
    float* out = (float*)d_out;

    int B = in_sizes[0] / (LH * DM);

    int nsm = 148;
    cudaDeviceGetAttribute(&nsm, cudaDevAttrMultiProcessorCount, 0);
    int grid = (nsm < B) ? nsm : B;

    cudaFuncSetAttribute(h2p_kernel, cudaFuncAttributeMaxDynamicSharedMemorySize, SMEM_BYTES);
    h2p_kernel<<<grid, 512, SMEM_BYTES>>>(hla_in, pep_in, W_hla, b_hla, W_pep, b_pep,
                                          rel_bias, ln_g, ln_b, W1, b1, W2, b2,
                                          W_out, b_out, out, B);
}

// round 8
// speedup vs baseline: 1.2313x; 1.2313x over previous
#include <cuda_runtime.h>
#include <cuda_bf16.h>

#define LH 128
#define LP 32
#define DM 64
#define HID 64
#define MAXLEN 128
#define QST 68     // Q fp32 row stride (floats)
#define KST 80     // KV fp32 row stride
#define HOFF 20    // KV per-head word offset

typedef unsigned long long u64;
typedef unsigned int u32;

// ---------------- smem layout ----------------
// float indices
#define BF   0        // bias cache [512]
#define QF   512      // Q fp32 [128][68]
#define KVF  9216     // KV fp32 [32][80]
#define WPF  11776    // W_pep fp32 [64][64]
// byte offsets (u32-array regions for bf16 tiles)
#define A0H_B  63488   // A hi  [128][72 bf16] (36 words/row)
#define A0L_B  81920   // A lo
#define H1_B   100352  // h1 single bf16 [128][136 bf16] (68 words/row)
#define WHH_B  135168  // W_hla^T hi [64][36w]
#define WHL_B  144384  // W_hla^T lo
#define W1T_B  153600  // W1^T single [128][36w]
#define W2T_B  172032  // W2^T single [64][68w]
#define WOH_B  189440  // W_out^T hi [64][36w]
#define WOL_B  198656  // W_out^T lo
#define SMEM_BYTES 207872

#define RWA 36   // words per row, K=64 arrays
#define RWH 68   // words per row, K=128 arrays

// bf16x2 pack: low half = a, high half = b
__device__ __forceinline__ u32 bf2pack(float a, float b) {
    u32 r;
    asm("cvt.rn.bf16x2.f32 %0, %1, %2;" : "=r"(r) : "f"(b), "f"(a));
    return r;
}
__device__ __forceinline__ void split2(float a, float b, u32& h, u32& l) {
    h = bf2pack(a, b);
    float ha = __uint_as_float(h << 16);
    float hb = __uint_as_float(h & 0xffff0000u);
    l = bf2pack(a - ha, b - hb);
}
__device__ __forceinline__ void split8(const float* x, uint4& h, uint4& l) {
    split2(x[0], x[1], h.x, l.x);
    split2(x[2], x[3], h.y, l.y);
    split2(x[4], x[5], h.z, l.z);
    split2(x[6], x[7], h.w, l.w);
}

__device__ __forceinline__ void mma16816(float d[4], const u32 a[4], u32 b0, u32 b1) {
    asm volatile(
        "mma.sync.aligned.m16n8k16.row.col.f32.bf16.bf16.f32 "
        "{%0,%1,%2,%3}, {%4,%5,%6,%7}, {%8,%9}, {%0,%1,%2,%3};"
        : "+f"(d[0]), "+f"(d[1]), "+f"(d[2]), "+f"(d[3])
        : "r"(a[0]), "r"(a[1]), "r"(a[2]), "r"(a[3]), "r"(b0), "r"(b1));
}
// A fragment: rows row..row+15, k = kt*16..+15
__device__ __forceinline__ void lda4(u32 a[4], const u32* A, int rw, int row, int kt,
                                     int lr, int lc) {
    const u32* p = A + (row + lr) * rw + kt * 8 + lc;
    a[0] = p[0]; a[2] = p[4];
    p += 8 * rw;
    a[1] = p[0]; a[3] = p[4];
}
// B fragment: cols n..n+7, k = kt*16..+15 (B^T stored n-major, k contiguous)
__device__ __forceinline__ void ldb2(u32 b[2], const u32* Bt, int rw, int n, int kt,
                                     int lr, int lc) {
    const u32* p = Bt + (n + lr) * rw + kt * 8 + lc;
    b[0] = p[0]; b[1] = p[4];
}

__global__ __launch_bounds__(512, 1)
void h2p_mma(const float* __restrict__ hla_in,
             const float* __restrict__ pep_in,
             const float* __restrict__ W_hla, const float* __restrict__ b_hla,
             const float* __restrict__ W_pep, const float* __restrict__ b_pep,
             const float* __restrict__ rel_bias,
             const float* __restrict__ ln_g, const float* __restrict__ ln_b,
             const float* __restrict__ W1, const float* __restrict__ b1,
             const float* __restrict__ W2, const float* __restrict__ b2,
             const float* __restrict__ W_out, const float* __restrict__ b_out,
             float* __restrict__ out, int B)
{
    extern __shared__ float sm[];
    char* smc = (char*)sm;
    const int t = threadIdx.x;
    const int w = t >> 5, lane = t & 31;
    const int lr = lane >> 2, lc = lane & 3;
    const int m0 = (w >> 1) * 16;        // warp's 16-row block
    const int nb = (w & 1);              // warp's n half

    u32* A0H = (u32*)(smc + A0H_B);
    u32* A0L = (u32*)(smc + A0L_B);
    u32* H1  = (u32*)(smc + H1_B);
    u32* WHH = (u32*)(smc + WHH_B);
    u32* WHL = (u32*)(smc + WHL_B);
    u32* W1T = (u32*)(smc + W1T_B);
    u32* W2T = (u32*)(smc + W2T_B);
    u32* WOH = (u32*)(smc + WOH_B);
    u32* WOL = (u32*)(smc + WOL_B);

    // ---------------- one-time init ----------------
    // bias cache
    {
        float v;
        if      (t < 64)  v = __ldg(b_hla + t);
        else if (t < 128) v = __ldg(b_pep + t - 64);
        else if (t < 256) v = __ldg(b1 + t - 128);
        else if (t < 320) v = __ldg(b2 + t - 256);
        else if (t < 384) v = __ldg(b_out + t - 320);
        else if (t < 448) v = __ldg(ln_g + t - 384);
        else              v = __ldg(ln_b + t - 448);
        sm[BF + t] = v;
    }
    // W_pep fp32 panel
    #pragma unroll
    for (int i = 0; i < 2; i++) {
        int idx = i * 512 + t;
        int k = idx >> 4, c = (idx & 15) * 4;
        *(float4*)&sm[WPF + k * 64 + c] = __ldg((const float4*)(W_pep + k * 64 + c));
    }
    // W_hla, W_out: transpose + hi/lo split
    {
        int n = t & 63, kg = t >> 6;   // kg 0..7, 8 k's
        float v[8];
        uint4 h4, l4;
        #pragma unroll
        for (int j = 0; j < 8; j++) v[j] = __ldg(W_hla + (kg * 8 + j) * 64 + n);
        split8(v, h4, l4);
        *(uint4*)&WHH[n * RWA + kg * 4] = h4;
        *(uint4*)&WHL[n * RWA + kg * 4] = l4;
        #pragma unroll
        for (int j = 0; j < 8; j++) v[j] = __ldg(W_out + (kg * 8 + j) * 64 + n);
        split8(v, h4, l4);
        *(uint4*)&WOH[n * RWA + kg * 4] = h4;
        *(uint4*)&WOL[n * RWA + kg * 4] = l4;
    }
    // W1 [64][128] -> W1t [128][36w] single bf16
    {
        int n = t & 127, kg = t >> 7;  // kg 0..3, 16 k's
        float v[16];
        #pragma unroll
        for (int j = 0; j < 16; j++) v[j] = __ldg(W1 + (kg * 16 + j) * 128 + n);
        u32 pk[8];
        #pragma unroll
        for (int i = 0; i < 8; i++) pk[i] = bf2pack(v[2*i], v[2*i+1]);
        *(uint4*)&W1T[n * RWA + kg * 8]     = make_uint4(pk[0], pk[1], pk[2], pk[3]);
        *(uint4*)&W1T[n * RWA + kg * 8 + 4] = make_uint4(pk[4], pk[5], pk[6], pk[7]);
    }
    // W2 [128][64] -> W2t [64][68w] single bf16
    {
        int n = t & 63, kg = t >> 6;   // kg 0..7, 16 k's
        float v[16];
        #pragma unroll
        for (int j = 0; j < 16; j++) v[j] = __ldg(W2 + (kg * 16 + j) * 64 + n);
        u32 pk[8];
        #pragma unroll
        for (int i = 0; i < 8; i++) pk[i] = bf2pack(v[2*i], v[2*i+1]);
        *(uint4*)&W2T[n * RWH + kg * 8]     = make_uint4(pk[0], pk[1], pk[2], pk[3]);
        *(uint4*)&W2T[n * RWH + kg * 8 + 4] = make_uint4(pk[4], pk[5], pk[6], pk[7]);
    }
    __syncthreads();

    for (int batch = blockIdx.x; batch < B; batch += gridDim.x) {
        // ======== stage: hla -> A0 hi/lo, pep -> Q[0:32) fp32 ========
        {
            const float4* hg = (const float4*)(hla_in + (size_t)batch * LH * DM);
            int row = t >> 2, cg = t & 3;
            float x[16];
            #pragma unroll
            for (int i = 0; i < 4; i++)
                *(float4*)&x[i * 4] = hg[row * 16 + cg * 4 + i];
            uint4 h4, l4;
            split8(x, h4, l4);
            *(uint4*)&A0H[row * RWA + cg * 8]     = h4;
            *(uint4*)&A0L[row * RWA + cg * 8]     = l4;
            split8(x + 8, h4, l4);
            *(uint4*)&A0H[row * RWA + cg * 8 + 4] = h4;
            *(uint4*)&A0L[row * RWA + cg * 8 + 4] = l4;

            const float4* pg = (const float4*)(pep_in + (size_t)batch * LP * DM);
            float4 pv = pg[t];
            int pr = t >> 4, pc = (t & 15) * 4;
            *(float4*)&sm[QF + pr * QST + pc] = pv;
        }
        __syncthreads();   // S0

        // ======== q GEMM (3-term) into regs; kv SIMT fp32 ========
        float Dq[4][4];
        {
            const int n0 = nb * 32;
            #pragma unroll
            for (int nt = 0; nt < 4; nt++) {
                int col = n0 + nt * 8 + 2 * lc;
                Dq[nt][0] = sm[BF + col];
                Dq[nt][1] = sm[BF + col + 1];
                Dq[nt][2] = Dq[nt][0];
                Dq[nt][3] = Dq[nt][1];
            }
            #pragma unroll
            for (int kt = 0; kt < 4; kt++) {
                u32 ah[4], al[4];
                lda4(ah, A0H, RWA, m0, kt, lr, lc);
                lda4(al, A0L, RWA, m0, kt, lr, lc);
                #pragma unroll
                for (int nt = 0; nt < 4; nt++) {
                    u32 bh[2], bl[2];
                    ldb2(bh, WHH, RWA, n0 + nt * 8, kt, lr, lc);
                    ldb2(bl, WHL, RWA, n0 + nt * 8, kt, lr, lc);
                    mma16816(Dq[nt], ah, bh[0], bh[1]);
                    mma16816(Dq[nt], al, bh[0], bh[1]);
                    mma16816(Dq[nt], ah, bl[0], bl[1]);
                }
            }
        }
        {   // kv = pep @ W_pep + b_pep (fp32)
            int lrow = t >> 4, c4 = (t & 15) * 4;
            float4 acc = *(const float4*)&sm[BF + 64 + c4];
            #pragma unroll 4
            for (int k0 = 0; k0 < 64; k0 += 4) {
                float4 a = *(const float4*)&sm[QF + lrow * QST + k0];
                #pragma unroll
                for (int j = 0; j < 4; j++) {
                    float av = (j == 0) ? a.x : (j == 1) ? a.y : (j == 2) ? a.z : a.w;
                    float4 wv = *(const float4*)&sm[WPF + (k0 + j) * 64 + c4];
                    acc.x = fmaf(av, wv.x, acc.x);
                    acc.y = fmaf(av, wv.y, acc.y);
                    acc.z = fmaf(av, wv.z, acc.z);
                    acc.w = fmaf(av, wv.w, acc.w);
                }
            }
            *(float4*)&sm[KVF + lrow * KST + (c4 >> 4) * HOFF + (c4 & 15)] = acc;
        }
        __syncthreads();   // S1 (kv done reading pep rows of Q)

        // ======== q -> Q fp32 ========
        {
            const int n0 = nb * 32;
            #pragma unroll
            for (int nt = 0; nt < 4; nt++) {
                int col = n0 + nt * 8 + 2 * lc;
                *(float2*)&sm[QF + (m0 + lr) * QST + col]     = make_float2(Dq[nt][0], Dq[nt][1]);
                *(float2*)&sm[QF + (m0 + lr + 8) * QST + col] = make_float2(Dq[nt][2], Dq[nt][3]);
            }
        }
        __syncthreads();   // S2

        // ======== attention + LN -> A0 hi/lo ========
        {
            const int r = t >> 2, h = t & 3;
            const float* qrow = &sm[QF + r * QST + h * 16];
            float q[16];
            #pragma unroll
            for (int i = 0; i < 4; i++)
                *(float4*)&q[i * 4] = *(const float4*)(qrow + i * 4);

            float sc[32];
            const float* brow = rel_bias + h * (MAXLEN * MAXLEN) + r * MAXLEN;
            #pragma unroll
            for (int k4 = 0; k4 < 8; k4++) {
                float4 bv = __ldg((const float4*)&brow[k4 * 4]);
                sc[k4*4+0] = bv.x; sc[k4*4+1] = bv.y;
                sc[k4*4+2] = bv.z; sc[k4*4+3] = bv.w;
            }
            #pragma unroll
            for (int k = 0; k < LP; k++) {
                const float* kr = &sm[KVF + k * KST + h * HOFF];
                float d = 0.f;
                #pragma unroll
                for (int i = 0; i < 16; i += 4) {
                    float4 v = *(const float4*)(kr + i);
                    d = fmaf(q[i+0], v.x, d);
                    d = fmaf(q[i+1], v.y, d);
                    d = fmaf(q[i+2], v.z, d);
                    d = fmaf(q[i+3], v.w, d);
                }
                sc[k] = fmaf(0.25f, d, sc[k]);
            }
            float mx = sc[0];
            #pragma unroll
            for (int k = 1; k < LP; k++) mx = fmaxf(mx, sc[k]);
            float ssum = 0.f;
            #pragma unroll
            for (int k = 0; k < LP; k++) { sc[k] = __expf(sc[k] - mx); ssum += sc[k]; }
            float inv = 1.0f / ssum;

            float cx[16];
            #pragma unroll
            for (int i = 0; i < 16; i++) cx[i] = 0.f;
            #pragma unroll
            for (int k = 0; k < LP; k++) {
                const float* kr = &sm[KVF + k * KST + h * HOFF];
                float p = sc[k];
                #pragma unroll
                for (int i = 0; i < 16; i += 4) {
                    float4 v = *(const float4*)(kr + i);
                    cx[i+0] = fmaf(p, v.x, cx[i+0]);
                    cx[i+1] = fmaf(p, v.y, cx[i+1]);
                    cx[i+2] = fmaf(p, v.z, cx[i+2]);
                    cx[i+3] = fmaf(p, v.w, cx[i+3]);
                }
            }
            float x[16];
            #pragma unroll
            for (int i = 0; i < 16; i++) x[i] = cx[i] * inv;

            float s1 = 0.f, s2 = 0.f;
            #pragma unroll
            for (int i = 0; i < 16; i++) { s1 += x[i]; s2 = fmaf(x[i], x[i], s2); }
            s1 += __shfl_xor_sync(0xffffffffu, s1, 1);
            s2 += __shfl_xor_sync(0xffffffffu, s2, 1);
            s1 += __shfl_xor_sync(0xffffffffu, s1, 2);
            s2 += __shfl_xor_sync(0xffffffffu, s2, 2);
            float mu   = s1 * (1.0f / 64.0f);
            float var  = s2 * (1.0f / 64.0f) - mu * mu;
            float rstd = rsqrtf(var + 1e-5f);
            float o[16];
            #pragma unroll
            for (int c4 = 0; c4 < 4; c4++) {
                float4 gv = *(const float4*)&sm[BF + 384 + h * 16 + c4 * 4];
                float4 bv = *(const float4*)&sm[BF + 448 + h * 16 + c4 * 4];
                o[c4*4+0] = (x[c4*4+0] - mu) * rstd * gv.x + bv.x;
                o[c4*4+1] = (x[c4*4+1] - mu) * rstd * gv.y + bv.y;
                o[c4*4+2] = (x[c4*4+2] - mu) * rstd * gv.z + bv.z;
                o[c4*4+3] = (x[c4*4+3] - mu) * rstd * gv.w + bv.w;
            }
            uint4 h4, l4;
            split8(o, h4, l4);
            *(uint4*)&A0H[r * RWA + h * 8]     = h4;
            *(uint4*)&A0L[r * RWA + h * 8]     = l4;
            split8(o + 8, h4, l4);
            *(uint4*)&A0H[r * RWA + h * 8 + 4] = h4;
            *(uint4*)&A0L[r * RWA + h * 8 + 4] = l4;
        }
        __syncthreads();   // S3

        // ======== h1 = gelu(LNctx @ W1 + b1) -> H1 (2-term A, single B) ========
        {
            const int n0 = nb * 64;
            float Dh[8][4];
            #pragma unroll
            for (int nt = 0; nt < 8; nt++) {
                int col = n0 + nt * 8 + 2 * lc;
                Dh[nt][0] = sm[BF + 128 + col];
                Dh[nt][1] = sm[BF + 128 + col + 1];
                Dh[nt][2] = Dh[nt][0];
                Dh[nt][3] = Dh[nt][1];
            }
            #pragma unroll
            for (int kt = 0; kt < 4; kt++) {
                u32 ah[4], al[4];
                lda4(ah, A0H, RWA, m0, kt, lr, lc);
                lda4(al, A0L, RWA, m0, kt, lr, lc);
                #pragma unroll
                for (int nt = 0; nt < 8; nt++) {
                    u32 bh[2];
                    ldb2(bh, W1T, RWA, n0 + nt * 8, kt, lr, lc);
                    mma16816(Dh[nt], ah, bh[0], bh[1]);
                    mma16816(Dh[nt], al, bh[0], bh[1]);
                }
            }
            #pragma unroll
            for (int nt = 0; nt < 8; nt++) {
                int cw = (n0 + nt * 8) / 2 + lc;   // word col
                float g0 = Dh[nt][0] * normcdff(Dh[nt][0]);
                float g1 = Dh[nt][1] * normcdff(Dh[nt][1]);
                float g2 = Dh[nt][2] * normcdff(Dh[nt][2]);
                float g3 = Dh[nt][3] * normcdff(Dh[nt][3]);
                H1[(m0 + lr) * RWH + cw]     = bf2pack(g0, g1);
                H1[(m0 + lr + 8) * RWH + cw] = bf2pack(g2, g3);
            }
        }
        __syncthreads();   // S4

        // ======== ffn = h1 @ W2 + b2 ; z = q + ffn -> A0 hi/lo ========
        {
            const int n0 = nb * 32;
            float Df[4][4];
            #pragma unroll
            for (int nt = 0; nt < 4; nt++) {
                int col = n0 + nt * 8 + 2 * lc;
                Df[nt][0] = sm[BF + 256 + col];
                Df[nt][1] = sm[BF + 256 + col + 1];
                Df[nt][2] = Df[nt][0];
                Df[nt][3] = Df[nt][1];
            }
            #pragma unroll
            for (int kt = 0; kt < 8; kt++) {
                u32 af[4];
                lda4(af, H1, RWH, m0, kt, lr, lc);
                #pragma unroll
                for (int nt = 0; nt < 4; nt++) {
                    u32 bh[2];
                    ldb2(bh, W2T, RWH, n0 + nt * 8, kt, lr, lc);
                    mma16816(Df[nt], af, bh[0], bh[1]);
                }
            }
            #pragma unroll
            for (int nt = 0; nt < 4; nt++) {
                int col = n0 + nt * 8 + 2 * lc;
                float2 q0 = *(const float2*)&sm[QF + (m0 + lr) * QST + col];
                float2 q1 = *(const float2*)&sm[QF + (m0 + lr + 8) * QST + col];
                float z0 = Df[nt][0] + q0.x, z1 = Df[nt][1] + q0.y;
                float z2 = Df[nt][2] + q1.x, z3 = Df[nt][3] + q1.y;
                int cw = col >> 1;
                u32 hh, ll;
                split2(z0, z1, hh, ll);
                A0H[(m0 + lr) * RWA + cw] = hh;
                A0L[(m0 + lr) * RWA + cw] = ll;
                split2(z2, z3, hh, ll);
                A0H[(m0 + lr + 8) * RWA + cw] = hh;
                A0L[(m0 + lr + 8) * RWA + cw] = ll;
            }
        }
        __syncthreads();   // S5

        // ======== out = z @ W_out + b_out (3-term) -> gmem ========
        {
            const int n0 = nb * 32;
            float Do[4][4];
            #pragma unroll
            for (int nt = 0; nt < 4; nt++) {
                int col = n0 + nt * 8 + 2 * lc;
                Do[nt][0] = sm[BF + 320 + col];
                Do[nt][1] = sm[BF + 320 + col + 1];
                Do[nt][2] = Do[nt][0];
                Do[nt][3] = Do[nt][1];
            }
            #pragma unroll
            for (int kt = 0; kt < 4; kt++) {
                u32 ah[4], al[4];
                lda4(ah, A0H, RWA, m0, kt, lr, lc);
                lda4(al, A0L, RWA, m0, kt, lr, lc);
                #pragma unroll
                for (int nt = 0; nt < 4; nt++) {
                    u32 bh[2], bl[2];
                    ldb2(bh, WOH, RWA, n0 + nt * 8, kt, lr, lc);
                    ldb2(bl, WOL, RWA, n0 + nt * 8, kt, lr, lc);
                    mma16816(Do[nt], ah, bh[0], bh[1]);
                    mma16816(Do[nt], al, bh[0], bh[1]);
                    mma16816(Do[nt], ah, bl[0], bl[1]);
                }
            }
            float* ob = out + (size_t)batch * LH * DM;
            #pragma unroll
            for (int nt = 0; nt < 4; nt++) {
                int col = n0 + nt * 8 + 2 * lc;
                *(float2*)&ob[(m0 + lr) * DM + col]     = make_float2(Do[nt][0], Do[nt][1]);
                *(float2*)&ob[(m0 + lr + 8) * DM + col] = make_float2(Do[nt][2], Do[nt][3]);
            }
        }
        __syncthreads();   // S6 (A0/Q free for next batch)
    }
}

extern "C" void kernel_launch(void* const* d_in, const int* in_sizes, int n_in,
                              void* d_out, int out_size)
{
    const float* hla_in   = (const float*)d_in[0];
    const float* pep_in   = (const float*)d_in[1];
    const float* W_hla    = (const float*)d_in[2];
    const float* b_hla    = (const float*)d_in[3];
    const float* W_pep    = (const float*)d_in[4];
    const float* b_pep    = (const float*)d_in[5];
    const float* rel_bias = (const float*)d_in[6];
    const float* ln_g     = (const float*)d_in[7];
    const float* ln_b     = (const float*)d_in[8];
    const float* W1       = (const float*)d_in[9];
    const float* b1       = (const float*)d_in[10];
    const float* W2       = (const float*)d_in[11];
    const float* b2       = (const float*)d_in[12];
    const float* W_out    = (const float*)d_in[13];
    const float* b_out    = (const float*)d_in[14];
    float* out = (float*)d_out;

    int B = in_sizes[0] / (LH * DM);

    int nsm = 148;
    cudaDeviceGetAttribute(&nsm, cudaDevAttrMultiProcessorCount, 0);
    int grid = (nsm < B) ? nsm : B;

    cudaFuncSetAttribute(h2p_mma, cudaFuncAttributeMaxDynamicSharedMemorySize, SMEM_BYTES);
    h2p_mma<<<grid, 512, SMEM_BYTES>>>(hla_in, pep_in, W_hla, b_hla, W_pep, b_pep,
                                       rel_bias, ln_g, ln_b, W1, b1, W2, b2,
                                       W_out, b_out, out, B);
}